// round 16
// baseline (speedup 1.0000x reference)
#include <cuda_runtime.h>
#include <cuda_fp16.h>

#define N_NODES 100000
#define F_IN    512
#define HIDDEN  64
#define TM      128
#define NBLK    ((N_NODES + TM - 1) / TM)   // 782
#define SLOTS   64
#define MAX_E   3200000
#define PTHR    128                          // place threads per CTA (4 warps)

// ---- static device scratch (zero at load; every call restores zeros) ----
__device__ __half              g_logh[(long long)N_NODES * HIDDEN];     // 12.8MB fp16 logits
__device__ unsigned long long  g_meta[(long long)N_NODES * SLOTS];      // 51.2MB (val<<32|col)
__device__ unsigned            g_cnt[N_NODES];
__device__ int                 g_ovf[MAX_E];
__device__ unsigned            g_ovf_n;
__device__ unsigned            g_ovf_n2;

// ---- packed f32x2 helpers ----
#define PACK2F(d, x)    asm("mov.b64 %0, {%1, %1};" : "=l"(d) : "r"(__float_as_uint(x)))
#define PACK2(d, a, b)  asm("mov.b64 %0, {%1, %2};" : "=l"(d) : "r"(__float_as_uint(a)), "r"(__float_as_uint(b)))
#define FMA2(acc, a, b) asm("fma.rn.f32x2 %0, %1, %2, %0;" : "+l"(acc) : "l"(a), "l"(b))

// smem layout for MLP: bf16 tiles, k-major [k][n], n-pitch padded to 72 bf16 = 144B
#define PITCH     144
#define OFF_W1HI  0
#define OFF_W1LO  73728
#define OFF_W2HI  147456
#define OFF_W2LO  156672
#define SMEM_TOTAL 165888

__device__ __forceinline__ unsigned smem_u32(const void* p) {
  unsigned a;
  asm("{ .reg .u64 t; cvta.to.shared.u64 t, %1; cvt.u32.u64 %0, t; }" : "=r"(a) : "l"(p));
  return a;
}
__device__ __forceinline__ void split2(float x, float y, unsigned &hi, unsigned &lo) {
  asm("cvt.rn.bf16x2.f32 %0, %1, %2;" : "=r"(hi) : "f"(y), "f"(x));
  float hx = __uint_as_float(hi << 16);
  float hy = __uint_as_float(hi & 0xFFFF0000u);
  asm("cvt.rn.bf16x2.f32 %0, %1, %2;" : "=r"(lo) : "f"(y - hy), "f"(x - hx));
}
__device__ __forceinline__ void ldmat4t(unsigned &r0, unsigned &r1, unsigned &r2,
                                        unsigned &r3, unsigned addr) {
  asm volatile("ldmatrix.sync.aligned.m8n8.x4.trans.shared.b16 {%0,%1,%2,%3}, [%4];"
               : "=r"(r0), "=r"(r1), "=r"(r2), "=r"(r3) : "r"(addr));
}
__device__ __forceinline__ void mma16816(float4 &c, unsigned a0, unsigned a1,
                                         unsigned a2, unsigned a3,
                                         unsigned b0, unsigned b1) {
  asm volatile("mma.sync.aligned.m16n8k16.row.col.f32.bf16.bf16.f32 "
               "{%0,%1,%2,%3}, {%4,%5,%6,%7}, {%8,%9}, {%0,%1,%2,%3};"
               : "+f"(c.x), "+f"(c.y), "+f"(c.z), "+f"(c.w)
               : "r"(a0), "r"(a1), "r"(a2), "r"(a3), "r"(b0), "r"(b1));
}
#define MLP_BAR() asm volatile("bar.sync 1, 256;" ::: "memory")

// ======= fused (R13 exact): warps 0-7 = HMMA MLP, warps 8-11 = place ========
__global__ __launch_bounds__(256 + PTHR) void fused_mlp_place(
    const float* __restrict__ X,
    const float* __restrict__ W1, const float* __restrict__ b1,
    const float* __restrict__ W2, const float* __restrict__ b2,
    const int* __restrict__ rows, const int* __restrict__ cols,
    const float* __restrict__ vals, int E)
{
  extern __shared__ unsigned char sm[];
  const int tid = threadIdx.x;

  if (tid >= 256) {
    // ---------------- place path (warps 8-11), R13 exact ----------------
    const int gtid = blockIdx.x * PTHR + (tid - 256);
    const int NP = gridDim.x * PTHR;
    for (int base = 0; base < E; base += NP * 16) {
      int r[16]; int cc[16]; float vv[16];
#pragma unroll
      for (int k = 0; k < 16; ++k) {
        int e = base + k * NP + gtid;
        bool ok = e < E;
        r[k]  = ok ? __ldg(rows + e) : -1;
        cc[k] = ok ? __ldg(cols + e) : 0;
        vv[k] = ok ? __ldg(vals + e) : 0.f;
      }
      unsigned pos[16];
#pragma unroll
      for (int k = 0; k < 16; ++k)
        pos[k] = (r[k] >= 0) ? atomicAdd(&g_cnt[r[k]], 1u) : 0u;
#pragma unroll
      for (int k = 0; k < 16; ++k) {
        if (r[k] >= 0) {
          if (pos[k] < SLOTS) {
            g_meta[(long long)r[k] * SLOTS + pos[k]] =
                ((unsigned long long)__float_as_uint(vv[k]) << 32) | (unsigned)cc[k];
          } else {
            unsigned oi = atomicAdd(&g_ovf_n, 1u);
            g_ovf[oi] = base + k * NP + gtid;
          }
        }
      }
    }
    return;
  }

  // ---------------- MLP path (warps 0-7, 256 threads; R13 exact) -----------
  const unsigned sb = smem_u32(sm);
  const int warp = tid >> 5;
  const unsigned lane = tid & 31;
  const int g  = lane >> 2;
  const int c2 = (lane & 3) * 2;

  for (int i = tid; i < F_IN * 32; i += 256) {
    int k = i >> 5, pr = i & 31;
    float2 w = __ldg((const float2*)(W1 + k * 64 + pr * 2));
    unsigned hi, lo; split2(w.x, w.y, hi, lo);
    *(unsigned*)(sm + OFF_W1HI + k * PITCH + pr * 4) = hi;
    *(unsigned*)(sm + OFF_W1LO + k * PITCH + pr * 4) = lo;
  }
  for (int i = tid; i < HIDDEN * 32; i += 256) {
    int k = i >> 5, pr = i & 31;
    float2 w = __ldg((const float2*)(W2 + k * 64 + pr * 2));
    unsigned hi, lo; split2(w.x, w.y, hi, lo);
    *(unsigned*)(sm + OFF_W2HI + k * PITCH + pr * 4) = hi;
    *(unsigned*)(sm + OFF_W2LO + k * PITCH + pr * 4) = lo;
  }
  MLP_BAR();

  const int mid = lane >> 3, mrow = lane & 7;
  const unsigned loff = (unsigned)(((mid & 1) * 8 + mrow) * PITCH + (mid >> 1) * 16);
  const unsigned bW1h = sb + OFF_W1HI + loff;
  const unsigned bW1l = sb + OFF_W1LO + loff;
  const unsigned bW2h = sb + OFF_W2HI + loff;
  const unsigned bW2l = sb + OFF_W2LO + loff;

  for (int blk = blockIdx.x; blk < NBLK; blk += gridDim.x) {
    const int r0 = blk * TM + warp * 16 + g;
    const int r1 = r0 + 8;
    const bool v0 = r0 < N_NODES, v1 = r1 < N_NODES;
    const float* px0 = X + (long long)r0 * F_IN + c2;
    const float* px1 = X + (long long)r1 * F_IN + c2;

    float4 acc[8];
#pragma unroll
    for (int j = 0; j < 8; ++j) acc[j] = make_float4(0.f, 0.f, 0.f, 0.f);

    const float2 z2 = make_float2(0.f, 0.f);
    float2 cx00 = v0 ? __ldg((const float2*)px0)       : z2;
    float2 cx01 = v0 ? __ldg((const float2*)(px0 + 8)) : z2;
    float2 cx10 = v1 ? __ldg((const float2*)px1)       : z2;
    float2 cx11 = v1 ? __ldg((const float2*)(px1 + 8)) : z2;

#pragma unroll 4
    for (int ks = 0; ks < 32; ++ks) {
      float2 n00 = z2, n01 = z2, n10 = z2, n11 = z2;
      if (ks < 31) {
        const float* q0 = px0 + (ks + 1) * 16;
        const float* q1 = px1 + (ks + 1) * 16;
        if (v0) { n00 = __ldg((const float2*)q0); n01 = __ldg((const float2*)(q0 + 8)); }
        if (v1) { n10 = __ldg((const float2*)q1); n11 = __ldg((const float2*)(q1 + 8)); }
      }
      unsigned aH0, aL0, aH1, aL1, aH2, aL2, aH3, aL3;
      split2(cx00.x, cx00.y, aH0, aL0);
      split2(cx10.x, cx10.y, aH1, aL1);
      split2(cx01.x, cx01.y, aH2, aL2);
      split2(cx11.x, cx11.y, aH3, aL3);

#pragma unroll
      for (int jj = 0; jj < 4; ++jj) {
        unsigned h0, h1, h2, h3, l0, l1, l2, l3;
        ldmat4t(h0, h1, h2, h3, bW1h + ks * (16 * PITCH) + jj * 32);
        ldmat4t(l0, l1, l2, l3, bW1l + ks * (16 * PITCH) + jj * 32);
        mma16816(acc[2 * jj],     aH0, aH1, aH2, aH3, h0, h1);
        mma16816(acc[2 * jj],     aH0, aH1, aH2, aH3, l0, l1);
        mma16816(acc[2 * jj],     aL0, aL1, aL2, aL3, h0, h1);
        mma16816(acc[2 * jj + 1], aH0, aH1, aH2, aH3, h2, h3);
        mma16816(acc[2 * jj + 1], aH0, aH1, aH2, aH3, l2, l3);
        mma16816(acc[2 * jj + 1], aL0, aL1, aL2, aL3, h2, h3);
      }
      cx00 = n00; cx01 = n01; cx10 = n10; cx11 = n11;
    }

    unsigned A2h[4][4], A2l[4][4];
#pragma unroll
    for (int j = 0; j < 8; ++j) {
      float2 bj = __ldg((const float2*)(b1 + 8 * j + c2));
      float x = fmaxf(acc[j].x + bj.x, 0.f);
      float y = fmaxf(acc[j].y + bj.y, 0.f);
      float z = fmaxf(acc[j].z + bj.x, 0.f);
      float w = fmaxf(acc[j].w + bj.y, 0.f);
      unsigned h0, l0, h1, l1;
      split2(x, y, h0, l0);
      split2(z, w, h1, l1);
      int kk = j >> 1, s = j & 1;
      A2h[kk][2 * s] = h0; A2h[kk][2 * s + 1] = h1;
      A2l[kk][2 * s] = l0; A2l[kk][2 * s + 1] = l1;
    }

    float4 acc2[8];
#pragma unroll
    for (int j = 0; j < 8; ++j) acc2[j] = make_float4(0.f, 0.f, 0.f, 0.f);
#pragma unroll
    for (int kk = 0; kk < 4; ++kk) {
#pragma unroll
      for (int jj = 0; jj < 4; ++jj) {
        unsigned h0, h1, h2, h3, l0, l1, l2, l3;
        ldmat4t(h0, h1, h2, h3, bW2h + kk * (16 * PITCH) + jj * 32);
        ldmat4t(l0, l1, l2, l3, bW2l + kk * (16 * PITCH) + jj * 32);
        mma16816(acc2[2 * jj],     A2h[kk][0], A2h[kk][1], A2h[kk][2], A2h[kk][3], h0, h1);
        mma16816(acc2[2 * jj],     A2h[kk][0], A2h[kk][1], A2h[kk][2], A2h[kk][3], l0, l1);
        mma16816(acc2[2 * jj],     A2l[kk][0], A2l[kk][1], A2l[kk][2], A2l[kk][3], h0, h1);
        mma16816(acc2[2 * jj + 1], A2h[kk][0], A2h[kk][1], A2h[kk][2], A2h[kk][3], h2, h3);
        mma16816(acc2[2 * jj + 1], A2h[kk][0], A2h[kk][1], A2h[kk][2], A2h[kk][3], l2, l3);
        mma16816(acc2[2 * jj + 1], A2l[kk][0], A2l[kk][1], A2l[kk][2], A2l[kk][3], h2, h3);
      }
    }

    // epilogue 2: + b2, convert to fp16, store half2 pairs
#pragma unroll
    for (int j = 0; j < 8; ++j) {
      float2 bj = __ldg((const float2*)(b2 + 8 * j + c2));
      if (v0) {
        float2 o = make_float2(acc2[j].x + bj.x, acc2[j].y + bj.y);
        *(__half2*)(g_logh + (long long)r0 * HIDDEN + 8 * j + c2) = __float22half2_rn(o);
      }
      if (v1) {
        float2 o = make_float2(acc2[j].z + bj.x, acc2[j].w + bj.y);
        *(__half2*)(g_logh + (long long)r1 * HIDDEN + 8 * j + c2) = __float22half2_rn(o);
      }
    }
  }
}

// ===== SpMM (R13 hot loop exact) + self-restoring counters ==================
__global__ __launch_bounds__(256) void spmm_kernel(float* __restrict__ out)
{
  const unsigned lane = threadIdx.x & 31;
  const int row = (blockIdx.x * blockDim.x + threadIdx.x) >> 5;
  if (row >= N_NODES) return;

  if (blockIdx.x == 0 && threadIdx.x == 0) {   // migrate + reset overflow count
    g_ovf_n2 = g_ovf_n;
    g_ovf_n = 0u;
  }

  unsigned nr = g_cnt[row];
  if (lane == 0) g_cnt[row] = 0u;              // restore zero for next call
  unsigned n = nr > SLOTS ? (unsigned)SLOTS : nr;
  const unsigned long long* base = g_meta + (long long)row * SLOTS;

  unsigned long long m0 = (lane < n)      ? base[lane]      : 0ULL;
  unsigned long long m1 = (lane + 32 < n) ? base[lane + 32] : 0ULL;

  unsigned long long accA = 0ULL, accB = 0ULL;
  const int n0 = (n < 32u) ? (int)n : 32;

#pragma unroll 4
  for (int e = 0; e < n0; ++e) {
    unsigned long long me = __shfl_sync(0xFFFFFFFFu, m0, e);
    unsigned c = (unsigned)me;
    float v = __uint_as_float((unsigned)(me >> 32));
    __half2 h2 = *(const __half2*)(g_logh + (long long)c * HIDDEN + 2 * lane);
    float2 pf = __half22float2(h2);
    unsigned long long p; PACK2(p, pf.x, pf.y);
    unsigned long long vv; PACK2F(vv, v);
    if (e & 1) { FMA2(accB, p, vv); } else { FMA2(accA, p, vv); }
  }
  const int n1 = (int)n - 32;
#pragma unroll 4
  for (int e = 0; e < n1; ++e) {
    unsigned long long me = __shfl_sync(0xFFFFFFFFu, m1, e);
    unsigned c = (unsigned)me;
    float v = __uint_as_float((unsigned)(me >> 32));
    __half2 h2 = *(const __half2*)(g_logh + (long long)c * HIDDEN + 2 * lane);
    float2 pf = __half22float2(h2);
    unsigned long long p; PACK2(p, pf.x, pf.y);
    unsigned long long vv; PACK2F(vv, v);
    if (e & 1) { FMA2(accB, p, vv); } else { FMA2(accA, p, vv); }
  }

  unsigned a_lo, a_hi, b_lo, b_hi;
  asm("mov.b64 {%0, %1}, %2;" : "=r"(a_lo), "=r"(a_hi) : "l"(accA));
  asm("mov.b64 {%0, %1}, %2;" : "=r"(b_lo), "=r"(b_hi) : "l"(accB));
  float2 res;
  res.x = __uint_as_float(a_lo) + __uint_as_float(b_lo);
  res.y = __uint_as_float(a_hi) + __uint_as_float(b_hi);
  *(float2*)(out + (long long)row * HIDDEN + 2 * lane) = res;
}

// exact fallback for rows with degree > SLOTS (statistically empty)
__global__ void ovf_kernel(const int* __restrict__ rows, const int* __restrict__ cols,
                           const float* __restrict__ vals, float* __restrict__ out)
{
  const unsigned n = g_ovf_n2;
  const int stride = gridDim.x * blockDim.x;
  for (unsigned j = blockIdx.x * blockDim.x + threadIdx.x; j < n; j += stride) {
    int i = g_ovf[j];
    int r = rows[i], c = cols[i];
    float v = vals[i];
#pragma unroll
    for (int k = 0; k < 16; ++k) {
      __half2 ha = *(const __half2*)(g_logh + (long long)c * HIDDEN + k * 4);
      __half2 hb = *(const __half2*)(g_logh + (long long)c * HIDDEN + k * 4 + 2);
      float2 fa = __half22float2(ha);
      float2 fb = __half22float2(hb);
      float* dst = out + (long long)r * HIDDEN + k * 4;
      asm volatile("red.global.add.v4.f32 [%0], {%1, %2, %3, %4};"
                   :: "l"(dst), "f"(fa.x * v), "f"(fa.y * v), "f"(fb.x * v), "f"(fb.y * v)
                   : "memory");
    }
  }
}

// ================= launch ====================================================
extern "C" void kernel_launch(void* const* d_in, const int* in_sizes, int n_in,
                              void* d_out, int out_size)
{
  const float* X     = (const float*)d_in[0];
  const int*   erows = (const int*)  d_in[1];
  const int*   ecols = (const int*)  d_in[2];
  const float* evals = (const float*)d_in[3];
  const float* W1    = (const float*)d_in[4];
  const float* b1    = (const float*)d_in[5];
  const float* W2    = (const float*)d_in[6];
  const float* b2    = (const float*)d_in[7];
  float* out = (float*)d_out;
  const int E = in_sizes[1];

  cudaFuncSetAttribute(fused_mlp_place, cudaFuncAttributeMaxDynamicSharedMemorySize, SMEM_TOTAL);

  fused_mlp_place<<<148, 256 + PTHR, SMEM_TOTAL>>>(X, W1, b1, W2, b2, erows, ecols, evals, E);
  spmm_kernel<<<(N_NODES * 32 + 255) / 256, 256>>>(out);
  ovf_kernel<<<64, 256>>>(erows, ecols, evals, out);
}

// round 17
// speedup vs baseline: 1.5649x; 1.5649x over previous
#include <cuda_runtime.h>
#include <cuda_fp16.h>

#define N_NODES 100000
#define F_IN    512
#define HIDDEN  64
#define TM      128
#define NBLK    ((N_NODES + TM - 1) / TM)   // 782
#define SLOTS   64
#define MAX_E   3200000
#define PTHR    128                          // place threads per CTA (4 warps)

// ---- static device scratch ----
__device__ __half              g_logh[(long long)N_NODES * HIDDEN];     // 12.8MB fp16 logits
__device__ unsigned long long  g_meta[(long long)N_NODES * SLOTS];      // 51.2MB (val<<32|col)
__device__ unsigned            g_cnt[N_NODES];
__device__ int                 g_ovf[MAX_E];
__device__ unsigned            g_ovf_n;

// ---- packed f32x2 helpers ----
#define PACK2F(d, x)    asm("mov.b64 %0, {%1, %1};" : "=l"(d) : "r"(__float_as_uint(x)))
#define PACK2(d, a, b)  asm("mov.b64 %0, {%1, %2};" : "=l"(d) : "r"(__float_as_uint(a)), "r"(__float_as_uint(b)))
#define FMA2(acc, a, b) asm("fma.rn.f32x2 %0, %1, %2, %0;" : "+l"(acc) : "l"(a), "l"(b))

// smem layout for MLP: bf16 tiles, k-major [k][n], n-pitch padded to 72 bf16 = 144B
#define PITCH     144
#define OFF_W1HI  0
#define OFF_W1LO  73728
#define OFF_W2HI  147456
#define OFF_W2LO  156672
#define SMEM_TOTAL 165888

__device__ __forceinline__ unsigned smem_u32(const void* p) {
  unsigned a;
  asm("{ .reg .u64 t; cvta.to.shared.u64 t, %1; cvt.u32.u64 %0, t; }" : "=r"(a) : "l"(p));
  return a;
}
__device__ __forceinline__ void split2(float x, float y, unsigned &hi, unsigned &lo) {
  asm("cvt.rn.bf16x2.f32 %0, %1, %2;" : "=r"(hi) : "f"(y), "f"(x));
  float hx = __uint_as_float(hi << 16);
  float hy = __uint_as_float(hi & 0xFFFF0000u);
  asm("cvt.rn.bf16x2.f32 %0, %1, %2;" : "=r"(lo) : "f"(y - hy), "f"(x - hx));
}
__device__ __forceinline__ void ldmat4t(unsigned &r0, unsigned &r1, unsigned &r2,
                                        unsigned &r3, unsigned addr) {
  asm volatile("ldmatrix.sync.aligned.m8n8.x4.trans.shared.b16 {%0,%1,%2,%3}, [%4];"
               : "=r"(r0), "=r"(r1), "=r"(r2), "=r"(r3) : "r"(addr));
}
__device__ __forceinline__ void mma16816(float4 &c, unsigned a0, unsigned a1,
                                         unsigned a2, unsigned a3,
                                         unsigned b0, unsigned b1) {
  asm volatile("mma.sync.aligned.m16n8k16.row.col.f32.bf16.bf16.f32 "
               "{%0,%1,%2,%3}, {%4,%5,%6,%7}, {%8,%9}, {%0,%1,%2,%3};"
               : "+f"(c.x), "+f"(c.y), "+f"(c.z), "+f"(c.w)
               : "r"(a0), "r"(a1), "r"(a2), "r"(a3), "r"(b0), "r"(b1));
}
#define MLP_BAR() asm volatile("bar.sync 1, 256;" ::: "memory")

// ================= init (R5 exact) ==========================================
__global__ void init_kernel()
{
  int i = blockIdx.x * blockDim.x + threadIdx.x;
  if (i < N_NODES) g_cnt[i] = 0u;
  if (i == 0) g_ovf_n = 0u;
}

// ======= fused: warps 0-7 = HMMA bf16x3 MLP, warps 8-11 = bucket place ======
__global__ __launch_bounds__(256 + PTHR) void fused_mlp_place(
    const float* __restrict__ X,
    const float* __restrict__ W1, const float* __restrict__ b1,
    const float* __restrict__ W2, const float* __restrict__ b2,
    const int* __restrict__ rows, const int* __restrict__ cols,
    const float* __restrict__ vals, int E)
{
  extern __shared__ unsigned char sm[];
  const int tid = threadIdx.x;

  if (tid >= 256) {
    // ---------------- place path (warps 8-11) ----------------
    const int gtid = blockIdx.x * PTHR + (tid - 256);
    const int NP = gridDim.x * PTHR;
    for (int base = 0; base < E; base += NP * 16) {
      int r[16]; int cc[16]; float vv[16];
#pragma unroll
      for (int k = 0; k < 16; ++k) {
        int e = base + k * NP + gtid;
        bool ok = e < E;
        r[k]  = ok ? __ldg(rows + e) : -1;
        cc[k] = ok ? __ldg(cols + e) : 0;
        vv[k] = ok ? __ldg(vals + e) : 0.f;
      }
      unsigned pos[16];
#pragma unroll
      for (int k = 0; k < 16; ++k)
        pos[k] = (r[k] >= 0) ? atomicAdd(&g_cnt[r[k]], 1u) : 0u;
#pragma unroll
      for (int k = 0; k < 16; ++k) {
        if (r[k] >= 0) {
          if (pos[k] < SLOTS) {
            g_meta[(long long)r[k] * SLOTS + pos[k]] =
                ((unsigned long long)__float_as_uint(vv[k]) << 32) | (unsigned)cc[k];
          } else {
            unsigned oi = atomicAdd(&g_ovf_n, 1u);
            g_ovf[oi] = base + k * NP + gtid;
          }
        }
      }
    }
    return;
  }

  // ---------------- MLP path (warps 0-7, 256 threads) ----------------
  const unsigned sb = smem_u32(sm);
  const int warp = tid >> 5;
  const unsigned lane = tid & 31;
  const int g  = lane >> 2;
  const int c2 = (lane & 3) * 2;

  for (int i = tid; i < F_IN * 32; i += 256) {
    int k = i >> 5, pr = i & 31;
    float2 w = __ldg((const float2*)(W1 + k * 64 + pr * 2));
    unsigned hi, lo; split2(w.x, w.y, hi, lo);
    *(unsigned*)(sm + OFF_W1HI + k * PITCH + pr * 4) = hi;
    *(unsigned*)(sm + OFF_W1LO + k * PITCH + pr * 4) = lo;
  }
  for (int i = tid; i < HIDDEN * 32; i += 256) {
    int k = i >> 5, pr = i & 31;
    float2 w = __ldg((const float2*)(W2 + k * 64 + pr * 2));
    unsigned hi, lo; split2(w.x, w.y, hi, lo);
    *(unsigned*)(sm + OFF_W2HI + k * PITCH + pr * 4) = hi;
    *(unsigned*)(sm + OFF_W2LO + k * PITCH + pr * 4) = lo;
  }
  MLP_BAR();

  const int mid = lane >> 3, mrow = lane & 7;
  const unsigned loff = (unsigned)(((mid & 1) * 8 + mrow) * PITCH + (mid >> 1) * 16);
  const unsigned bW1h = sb + OFF_W1HI + loff;
  const unsigned bW1l = sb + OFF_W1LO + loff;
  const unsigned bW2h = sb + OFF_W2HI + loff;
  const unsigned bW2l = sb + OFF_W2LO + loff;

  for (int blk = blockIdx.x; blk < NBLK; blk += gridDim.x) {
    const int r0 = blk * TM + warp * 16 + g;
    const int r1 = r0 + 8;
    const bool v0 = r0 < N_NODES, v1 = r1 < N_NODES;
    const float* px0 = X + (long long)r0 * F_IN + c2;
    const float* px1 = X + (long long)r1 * F_IN + c2;

    float4 acc[8];
#pragma unroll
    for (int j = 0; j < 8; ++j) acc[j] = make_float4(0.f, 0.f, 0.f, 0.f);

    const float2 z2 = make_float2(0.f, 0.f);
    float2 cx00 = v0 ? __ldg((const float2*)px0)       : z2;
    float2 cx01 = v0 ? __ldg((const float2*)(px0 + 8)) : z2;
    float2 cx10 = v1 ? __ldg((const float2*)px1)       : z2;
    float2 cx11 = v1 ? __ldg((const float2*)(px1 + 8)) : z2;

#pragma unroll 4
    for (int ks = 0; ks < 32; ++ks) {
      float2 n00 = z2, n01 = z2, n10 = z2, n11 = z2;
      if (ks < 31) {
        const float* q0 = px0 + (ks + 1) * 16;
        const float* q1 = px1 + (ks + 1) * 16;
        if (v0) { n00 = __ldg((const float2*)q0); n01 = __ldg((const float2*)(q0 + 8)); }
        if (v1) { n10 = __ldg((const float2*)q1); n11 = __ldg((const float2*)(q1 + 8)); }
      }
      unsigned aH0, aL0, aH1, aL1, aH2, aL2, aH3, aL3;
      split2(cx00.x, cx00.y, aH0, aL0);
      split2(cx10.x, cx10.y, aH1, aL1);
      split2(cx01.x, cx01.y, aH2, aL2);
      split2(cx11.x, cx11.y, aH3, aL3);

#pragma unroll
      for (int jj = 0; jj < 4; ++jj) {
        unsigned h0, h1, h2, h3, l0, l1, l2, l3;
        ldmat4t(h0, h1, h2, h3, bW1h + ks * (16 * PITCH) + jj * 32);
        ldmat4t(l0, l1, l2, l3, bW1l + ks * (16 * PITCH) + jj * 32);
        mma16816(acc[2 * jj],     aH0, aH1, aH2, aH3, h0, h1);
        mma16816(acc[2 * jj],     aH0, aH1, aH2, aH3, l0, l1);
        mma16816(acc[2 * jj],     aL0, aL1, aL2, aL3, h0, h1);
        mma16816(acc[2 * jj + 1], aH0, aH1, aH2, aH3, h2, h3);
        mma16816(acc[2 * jj + 1], aH0, aH1, aH2, aH3, l2, l3);
        mma16816(acc[2 * jj + 1], aL0, aL1, aL2, aL3, h2, h3);
      }
      cx00 = n00; cx01 = n01; cx10 = n10; cx11 = n11;
    }

    unsigned A2h[4][4], A2l[4][4];
#pragma unroll
    for (int j = 0; j < 8; ++j) {
      float2 bj = __ldg((const float2*)(b1 + 8 * j + c2));
      float x = fmaxf(acc[j].x + bj.x, 0.f);
      float y = fmaxf(acc[j].y + bj.y, 0.f);
      float z = fmaxf(acc[j].z + bj.x, 0.f);
      float w = fmaxf(acc[j].w + bj.y, 0.f);
      unsigned h0, l0, h1, l1;
      split2(x, y, h0, l0);
      split2(z, w, h1, l1);
      int kk = j >> 1, s = j & 1;
      A2h[kk][2 * s] = h0; A2h[kk][2 * s + 1] = h1;
      A2l[kk][2 * s] = l0; A2l[kk][2 * s + 1] = l1;
    }

    float4 acc2[8];
#pragma unroll
    for (int j = 0; j < 8; ++j) acc2[j] = make_float4(0.f, 0.f, 0.f, 0.f);
#pragma unroll
    for (int kk = 0; kk < 4; ++kk) {
#pragma unroll
      for (int jj = 0; jj < 4; ++jj) {
        unsigned h0, h1, h2, h3, l0, l1, l2, l3;
        ldmat4t(h0, h1, h2, h3, bW2h + kk * (16 * PITCH) + jj * 32);
        ldmat4t(l0, l1, l2, l3, bW2l + kk * (16 * PITCH) + jj * 32);
        mma16816(acc2[2 * jj],     A2h[kk][0], A2h[kk][1], A2h[kk][2], A2h[kk][3], h0, h1);
        mma16816(acc2[2 * jj],     A2h[kk][0], A2h[kk][1], A2h[kk][2], A2h[kk][3], l0, l1);
        mma16816(acc2[2 * jj],     A2l[kk][0], A2l[kk][1], A2l[kk][2], A2l[kk][3], h0, h1);
        mma16816(acc2[2 * jj + 1], A2h[kk][0], A2h[kk][1], A2h[kk][2], A2h[kk][3], h2, h3);
        mma16816(acc2[2 * jj + 1], A2h[kk][0], A2h[kk][1], A2h[kk][2], A2h[kk][3], l2, l3);
        mma16816(acc2[2 * jj + 1], A2l[kk][0], A2l[kk][1], A2l[kk][2], A2l[kk][3], h2, h3);
      }
    }

    // epilogue 2: + b2, convert to fp16, store half2 pairs
#pragma unroll
    for (int j = 0; j < 8; ++j) {
      float2 bj = __ldg((const float2*)(b2 + 8 * j + c2));
      if (v0) {
        float2 o = make_float2(acc2[j].x + bj.x, acc2[j].y + bj.y);
        *(__half2*)(g_logh + (long long)r0 * HIDDEN + 8 * j + c2) = __float22half2_rn(o);
      }
      if (v1) {
        float2 o = make_float2(acc2[j].z + bj.x, acc2[j].w + bj.y);
        *(__half2*)(g_logh + (long long)r1 * HIDDEN + 8 * j + c2) = __float22half2_rn(o);
      }
    }
  }
}

// ===== SpMM: R5-exact structure; gather fp16 logits (half traffic) ==========
__global__ __launch_bounds__(256) void spmm_kernel(float* __restrict__ out)
{
  const unsigned lane = threadIdx.x & 31;
  const int row = (blockIdx.x * blockDim.x + threadIdx.x) >> 5;
  if (row >= N_NODES) return;

  unsigned n = g_cnt[row];
  if (n > SLOTS) n = SLOTS;
  const unsigned long long* base = g_meta + (long long)row * SLOTS;

  unsigned long long m0 = (lane < n)      ? base[lane]      : 0ULL;
  unsigned long long m1 = (lane + 32 < n) ? base[lane + 32] : 0ULL;

  unsigned long long accA = 0ULL, accB = 0ULL;
  const int n0 = (n < 32u) ? (int)n : 32;

#pragma unroll 4
  for (int e = 0; e < n0; ++e) {
    unsigned long long me = __shfl_sync(0xFFFFFFFFu, m0, e);
    unsigned c = (unsigned)me;
    float v = __uint_as_float((unsigned)(me >> 32));
    __half2 h2 = *(const __half2*)(g_logh + (long long)c * HIDDEN + 2 * lane);
    float2 pf = __half22float2(h2);
    unsigned long long p; PACK2(p, pf.x, pf.y);
    unsigned long long vv; PACK2F(vv, v);
    if (e & 1) { FMA2(accB, p, vv); } else { FMA2(accA, p, vv); }
  }
  const int n1 = (int)n - 32;
#pragma unroll 4
  for (int e = 0; e < n1; ++e) {
    unsigned long long me = __shfl_sync(0xFFFFFFFFu, m1, e);
    unsigned c = (unsigned)me;
    float v = __uint_as_float((unsigned)(me >> 32));
    __half2 h2 = *(const __half2*)(g_logh + (long long)c * HIDDEN + 2 * lane);
    float2 pf = __half22float2(h2);
    unsigned long long p; PACK2(p, pf.x, pf.y);
    unsigned long long vv; PACK2F(vv, v);
    if (e & 1) { FMA2(accB, p, vv); } else { FMA2(accA, p, vv); }
  }

  unsigned a_lo, a_hi, b_lo, b_hi;
  asm("mov.b64 {%0, %1}, %2;" : "=r"(a_lo), "=r"(a_hi) : "l"(accA));
  asm("mov.b64 {%0, %1}, %2;" : "=r"(b_lo), "=r"(b_hi) : "l"(accB));
  float2 res;
  res.x = __uint_as_float(a_lo) + __uint_as_float(b_lo);
  res.y = __uint_as_float(a_hi) + __uint_as_float(b_hi);
  *(float2*)(out + (long long)row * HIDDEN + 2 * lane) = res;
}

// exact fallback for rows with degree > SLOTS (statistically empty)
__global__ void ovf_kernel(const int* __restrict__ rows, const int* __restrict__ cols,
                           const float* __restrict__ vals, float* __restrict__ out)
{
  const unsigned n = g_ovf_n;
  const int stride = gridDim.x * blockDim.x;
  for (unsigned j = blockIdx.x * blockDim.x + threadIdx.x; j < n; j += stride) {
    int i = g_ovf[j];
    int r = rows[i], c = cols[i];
    float v = vals[i];
#pragma unroll
    for (int k = 0; k < 16; ++k) {
      __half2 ha = *(const __half2*)(g_logh + (long long)c * HIDDEN + k * 4);
      __half2 hb = *(const __half2*)(g_logh + (long long)c * HIDDEN + k * 4 + 2);
      float2 fa = __half22float2(ha);
      float2 fb = __half22float2(hb);
      float* dst = out + (long long)r * HIDDEN + k * 4;
      asm volatile("red.global.add.v4.f32 [%0], {%1, %2, %3, %4};"
                   :: "l"(dst), "f"(fa.x * v), "f"(fa.y * v), "f"(fb.x * v), "f"(fb.y * v)
                   : "memory");
    }
  }
}

// ================= launch ====================================================
extern "C" void kernel_launch(void* const* d_in, const int* in_sizes, int n_in,
                              void* d_out, int out_size)
{
  const float* X     = (const float*)d_in[0];
  const int*   erows = (const int*)  d_in[1];
  const int*   ecols = (const int*)  d_in[2];
  const float* evals = (const float*)d_in[3];
  const float* W1    = (const float*)d_in[4];
  const float* b1    = (const float*)d_in[5];
  const float* W2    = (const float*)d_in[6];
  const float* b2    = (const float*)d_in[7];
  float* out = (float*)d_out;
  const int E = in_sizes[1];

  cudaFuncSetAttribute(fused_mlp_place, cudaFuncAttributeMaxDynamicSharedMemorySize, SMEM_TOTAL);

  init_kernel<<<(N_NODES + 255) / 256, 256>>>();
  fused_mlp_place<<<148, 256 + PTHR, SMEM_TOTAL>>>(X, W1, b1, W2, b2, erows, ecols, evals, E);
  spmm_kernel<<<(N_NODES * 32 + 255) / 256, 256>>>(out);
  ovf_kernel<<<64, 256>>>(erows, ecols, evals, out);
}